// round 8
// baseline (speedup 1.0000x reference)
#include <cuda_runtime.h>

// LIF spike scan: x [B=64, T=8, C=128, H=32, W=32] fp32
// Per spatial site: mem = mem*TAU + x_t; spike = (mem > THRESH); mem = (1-spike)*mem
// Pure HBM streaming (512 MiB compulsory). Persistent grid-stride at one full
// residency (148 SMs x 6 CTAs = 888) to kill wave-transition raggedness of the
// 9.2-wave 8192-CTA launch. Plain LDG/STG (.cs hints measured -3% in R4),
// int32 addressing, 8-deep front-batched loads per iteration.

#define B_DIM 64
#define T_DIM 8
#define CHW4  (128 * 32 * 32 / 4)   // 32768 float4 per (b,t) slab
#define NSPATIAL4 (B_DIM * CHW4)    // 2,097,152 float4 sites

#define NUM_SMS   148
#define CTAS_PER_SM 6
#define GRID_CTAS (NUM_SMS * CTAS_PER_SM)   // 888

__global__ __launch_bounds__(256) void lif_kernel(
    const float4* __restrict__ x, float4* __restrict__ out)
{
    const float TAU = 0.5f;
    const float THRESH = 1.0f;
    const int stride = GRID_CTAS * 256;

    for (int i = blockIdx.x * 256 + threadIdx.x; i < NSPATIAL4; i += stride) {
        // i = b * CHW4 + rem  (CHW4 = 2^15 -> shifts); all 32-bit.
        const int b    = i >> 15;
        const int rem  = i & (CHW4 - 1);
        const int base = b * (T_DIM * CHW4) + rem;   // max 16.7M float4 < 2^31

        // Front-batch all 8 strided loads (MLP=8, independent addresses).
        float4 xt[T_DIM];
#pragma unroll
        for (int t = 0; t < T_DIM; t++)
            xt[t] = x[base + t * CHW4];

        float4 mem = make_float4(0.f, 0.f, 0.f, 0.f);
#pragma unroll
        for (int t = 0; t < T_DIM; t++) {
            float4 s;
            mem.x = fmaf(mem.x, TAU, xt[t].x);
            mem.y = fmaf(mem.y, TAU, xt[t].y);
            mem.z = fmaf(mem.z, TAU, xt[t].z);
            mem.w = fmaf(mem.w, TAU, xt[t].w);

            s.x = (mem.x > THRESH) ? 1.0f : 0.0f;
            s.y = (mem.y > THRESH) ? 1.0f : 0.0f;
            s.z = (mem.z > THRESH) ? 1.0f : 0.0f;
            s.w = (mem.w > THRESH) ? 1.0f : 0.0f;

            // hard reset: mem = (1 - spike) * mem
            mem.x = (s.x > 0.f) ? 0.f : mem.x;
            mem.y = (s.y > 0.f) ? 0.f : mem.y;
            mem.z = (s.z > 0.f) ? 0.f : mem.z;
            mem.w = (s.w > 0.f) ? 0.f : mem.w;

            out[base + t * CHW4] = s;
        }
    }
}

extern "C" void kernel_launch(void* const* d_in, const int* in_sizes, int n_in,
                              void* d_out, int out_size)
{
    const float4* x = (const float4*)d_in[0];
    float4* out = (float4*)d_out;
    lif_kernel<<<GRID_CTAS, 256>>>(x, out);
}

// round 9
// speedup vs baseline: 1.1512x; 1.1512x over previous
#include <cuda_runtime.h>

// LIF spike scan: x [B=64, T=8, C=128, H=32, W=32] fp32
// Per spatial site: mem = mem*TAU + x_t; spike = (mem > THRESH); mem = (1-spike)*mem
//
// Pure HBM streaming: 512 MiB compulsory traffic. Measured at 6.3 TB/s =
// the B200 LTS throughput cap (~6300 B/cyc, path-independent), i.e. at the
// chip roofline for this pattern. Ruled out by measurement:
//   - .cs streaming hints: -3% (R4)
//   - persistent grid-stride: -12% (R8; breaks cross-iteration load batching)
// Config: one-shot 8192x256 launch, 8-deep front-batched LDG.128 (MLP=8,
// ~49KB/SM outstanding covers DRAM latency), int32 addressing, plain LDG/STG.

#define B_DIM 64
#define T_DIM 8
#define CHW4  (128 * 32 * 32 / 4)   // 32768 float4 per (b,t) slab
#define NSPATIAL4 (B_DIM * CHW4)    // 2,097,152 float4 sites

__global__ __launch_bounds__(256) void lif_kernel(
    const float4* __restrict__ x, float4* __restrict__ out)
{
    const int i = blockIdx.x * blockDim.x + threadIdx.x;
    if (i >= NSPATIAL4) return;

    // i = b * CHW4 + rem  (CHW4 = 2^15 -> shifts); all 32-bit.
    const int b    = i >> 15;
    const int rem  = i & (CHW4 - 1);
    const int base = b * (T_DIM * CHW4) + rem;   // max 16.7M float4 < 2^31

    // Front-batch all 8 strided loads (MLP=8, independent addresses).
    float4 xt[T_DIM];
#pragma unroll
    for (int t = 0; t < T_DIM; t++)
        xt[t] = x[base + t * CHW4];

    const float TAU = 0.5f;
    const float THRESH = 1.0f;

    float4 mem = make_float4(0.f, 0.f, 0.f, 0.f);
#pragma unroll
    for (int t = 0; t < T_DIM; t++) {
        float4 s;
        mem.x = fmaf(mem.x, TAU, xt[t].x);
        mem.y = fmaf(mem.y, TAU, xt[t].y);
        mem.z = fmaf(mem.z, TAU, xt[t].z);
        mem.w = fmaf(mem.w, TAU, xt[t].w);

        s.x = (mem.x > THRESH) ? 1.0f : 0.0f;
        s.y = (mem.y > THRESH) ? 1.0f : 0.0f;
        s.z = (mem.z > THRESH) ? 1.0f : 0.0f;
        s.w = (mem.w > THRESH) ? 1.0f : 0.0f;

        // hard reset: mem = (1 - spike) * mem
        mem.x = (s.x > 0.f) ? 0.f : mem.x;
        mem.y = (s.y > 0.f) ? 0.f : mem.y;
        mem.z = (s.z > 0.f) ? 0.f : mem.z;
        mem.w = (s.w > 0.f) ? 0.f : mem.w;

        out[base + t * CHW4] = s;
    }
}

extern "C" void kernel_launch(void* const* d_in, const int* in_sizes, int n_in,
                              void* d_out, int out_size)
{
    const float4* x = (const float4*)d_in[0];
    float4* out = (float4*)d_out;
    const int threads = 256;
    const int blocks = (NSPATIAL4 + threads - 1) / threads;  // 8192
    lif_kernel<<<blocks, threads>>>(x, out);
}